// round 1
// baseline (speedup 1.0000x reference)
#include <cuda_runtime.h>
#include <cuda_fp16.h>
#include <cstdint>

// ---------------------------------------------------------------------------
// Problem dims (fixed shapes for this problem instance)
// ---------------------------------------------------------------------------
static constexpr int T_ = 8192;   // tokens (M)
static constexpr int O_ = 4096;   // out features (N)
static constexpr int I_ = 4096;   // in features (K)
static constexpr int GROUP_ = 256;
static constexpr int G_ = I_ / GROUP_;  // 16 groups per row

// ---------------------------------------------------------------------------
// Scratch (device globals — no runtime allocation allowed)
//   g_xq : (q - zp) per activation element, exact integer in fp16 (|v|<=255)
//   g_wq : dequantized weight (w - z)*s in fp16
//   g_sx : per-token activation scale (folded in at GEMM epilogue)
// ---------------------------------------------------------------------------
__device__ __half g_xq[(size_t)T_ * I_];
__device__ __half g_wq[(size_t)O_ * I_];
__device__ float  g_sx[T_];

// ---------------------------------------------------------------------------
// PTX helpers
// ---------------------------------------------------------------------------
__device__ __forceinline__ void cp_async16(uint32_t saddr, const void* gptr) {
    asm volatile("cp.async.cg.shared.global [%0], [%1], 16;\n"
                 :: "r"(saddr), "l"(gptr) : "memory");
}
__device__ __forceinline__ void cp_commit() {
    asm volatile("cp.async.commit_group;\n" ::: "memory");
}
template <int N>
__device__ __forceinline__ void cp_wait() {
    asm volatile("cp.async.wait_group %0;\n" :: "n"(N) : "memory");
}
__device__ __forceinline__ void ldmatrix_x4(uint32_t (&r)[4], uint32_t addr) {
    asm volatile("ldmatrix.sync.aligned.m8n8.x4.shared.b16 {%0,%1,%2,%3}, [%4];\n"
                 : "=r"(r[0]), "=r"(r[1]), "=r"(r[2]), "=r"(r[3]) : "r"(addr));
}
__device__ __forceinline__ void mma16816(float (&d)[4], const uint32_t (&a)[4],
                                         uint32_t b0, uint32_t b1) {
    asm volatile(
        "mma.sync.aligned.m16n8k16.row.col.f32.f16.f16.f32 "
        "{%0,%1,%2,%3}, {%4,%5,%6,%7}, {%8,%9}, {%0,%1,%2,%3};\n"
        : "+f"(d[0]), "+f"(d[1]), "+f"(d[2]), "+f"(d[3])
        : "r"(a[0]), "r"(a[1]), "r"(a[2]), "r"(a[3]), "r"(b0), "r"(b1));
}

// ---------------------------------------------------------------------------
// Kernel 1: per-token asymmetric int8 fake-quant of x.
// Matches torchao/jax reference exactly (IEEE div, rint = round-half-even).
// Stores (q - zp) as fp16 (exact integer) and sx per row.
// One block (256 threads) per token row of 4096 floats.
// ---------------------------------------------------------------------------
__global__ void __launch_bounds__(256) quant_x_kernel(const float* __restrict__ x) {
    const int row = blockIdx.x;
    const int tid = threadIdx.x;
    const float4* xr = reinterpret_cast<const float4*>(x) + (size_t)row * (I_ / 4);

    float4 v[4];
    float mn = 0.0f, mx = 0.0f;   // reference takes min(.,0) / max(.,0)
#pragma unroll
    for (int j = 0; j < 4; ++j) {
        v[j] = xr[tid + 256 * j];
        mn = fminf(mn, fminf(fminf(v[j].x, v[j].y), fminf(v[j].z, v[j].w)));
        mx = fmaxf(mx, fmaxf(fmaxf(v[j].x, v[j].y), fmaxf(v[j].z, v[j].w)));
    }
#pragma unroll
    for (int o = 16; o > 0; o >>= 1) {
        mn = fminf(mn, __shfl_xor_sync(0xffffffffu, mn, o));
        mx = fmaxf(mx, __shfl_xor_sync(0xffffffffu, mx, o));
    }
    __shared__ float smn[8], smx[8];
    if ((tid & 31) == 0) { smn[tid >> 5] = mn; smx[tid >> 5] = mx; }
    __syncthreads();
    mn = smn[0]; mx = smx[0];
#pragma unroll
    for (int w = 1; w < 8; ++w) { mn = fminf(mn, smn[w]); mx = fmaxf(mx, smx[w]); }

    const float scale = fmaxf(__fdiv_rn(mx - mn, 255.0f), 1.1920929e-07f);
    const float dmin = __fdiv_rn(mn, scale);
    const float dmax = __fdiv_rn(mx, scale);
    float zp = ((-128.0f + dmin) + (127.0f + dmax) > 0.0f) ? (-128.0f - dmin)
                                                           : (127.0f - dmax);
    zp = rintf(fminf(fmaxf(zp, -128.0f), 127.0f));

    __half* out = g_xq + (size_t)row * I_;
#pragma unroll
    for (int j = 0; j < 4; ++j) {
        float f[4] = {v[j].x, v[j].y, v[j].z, v[j].w};
        __align__(8) __half h[4];
#pragma unroll
        for (int e = 0; e < 4; ++e) {
            float q = rintf(__fdiv_rn(f[e], scale)) + zp;
            q = fminf(fmaxf(q, -128.0f), 127.0f);
            h[e] = __float2half_rn(q - zp);   // integer in [-255,255]: exact in fp16
        }
        *reinterpret_cast<uint2*>(out + (size_t)(tid + 256 * j) * 4) =
            *reinterpret_cast<const uint2*>(h);
    }
    if (tid == 0) g_sx[row] = scale;
}

// ---------------------------------------------------------------------------
// Kernel 2: groupwise int4 weight dequant -> fp16. 8 elements per thread.
// ---------------------------------------------------------------------------
__global__ void __launch_bounds__(256) dequant_w_kernel(const int* __restrict__ w,
                                                        const float* __restrict__ scales,
                                                        const float* __restrict__ zeros) {
    const int t = blockIdx.x * 256 + threadIdx.x;   // 0 .. O_*I_/8
    const int row = t >> 9;          // I_/8 = 512 chunks per row
    const int col = (t & 511) << 3;
    const int g = col >> 8;
    const float s = scales[row * G_ + g];
    const float z = zeros[row * G_ + g];
    const int4* wp = reinterpret_cast<const int4*>(w + (size_t)row * I_ + col);
    const int4 a = wp[0], b = wp[1];
    __align__(16) __half h[8];
    h[0] = __float2half_rn(((float)a.x - z) * s);
    h[1] = __float2half_rn(((float)a.y - z) * s);
    h[2] = __float2half_rn(((float)a.z - z) * s);
    h[3] = __float2half_rn(((float)a.w - z) * s);
    h[4] = __float2half_rn(((float)b.x - z) * s);
    h[5] = __float2half_rn(((float)b.y - z) * s);
    h[6] = __float2half_rn(((float)b.z - z) * s);
    h[7] = __float2half_rn(((float)b.w - z) * s);
    *reinterpret_cast<uint4*>(g_wq + (size_t)row * I_ + col) =
        *reinterpret_cast<const uint4*>(h);
}

// ---------------------------------------------------------------------------
// Kernel 3: fp16 GEMM  C[t,o] = sx[t] * sum_k xq[t,k] * wq[o,k]
// A = g_xq [M,K] row-major (K contiguous), B = g_wq [N,K] row-major -> TN gemm.
// 128x128x32 tile, 256 threads (2x4 warps, 64x32 warp tile), cp.async double
// buffer, XOR swizzle for conflict-free ldmatrix.
// ---------------------------------------------------------------------------
static constexpr int BM = 128;
static constexpr int BN = 128;
static constexpr int BK = 32;

// SMEM tile row = 32 halves = 64B = four 16B chunks. Swizzle chunk by (row>>1)&3
// so 8 consecutive rows hit 8 distinct 16B phases (conflict-free LDSM & STS).
__device__ __forceinline__ uint32_t swz(uint32_t row, uint32_t chunk) {
    return row * 64u + ((chunk ^ ((row >> 1) & 3u)) << 4);
}

__global__ void __launch_bounds__(256, 2) gemm_kernel(float* __restrict__ C) {
    __shared__ __align__(128) __half sA[2][BM * BK];
    __shared__ __align__(128) __half sB[2][BN * BK];

    const int tid = threadIdx.x;
    const int bm = blockIdx.y, bn = blockIdx.x;
    const int lane = tid & 31;
    const int wid = tid >> 5;
    const int wm = wid >> 2;      // 0..1  (64 rows each)
    const int wn = wid & 3;       // 0..3  (32 cols each)

    const uint32_t saA0 = (uint32_t)__cvta_generic_to_shared(&sA[0][0]);
    const uint32_t saB0 = (uint32_t)__cvta_generic_to_shared(&sB[0][0]);

    const __half* Ag = g_xq + (size_t)(bm * BM) * I_;
    const __half* Bg = g_wq + (size_t)(bn * BN) * I_;

    const int ldrow = tid >> 2;   // 0..63
    const int ldch = tid & 3;     // 0..3

    float acc[4][4][4];
#pragma unroll
    for (int a = 0; a < 4; ++a)
#pragma unroll
        for (int b = 0; b < 4; ++b)
#pragma unroll
            for (int c = 0; c < 4; ++c) acc[a][b][c] = 0.0f;

    auto load_stage = [&](int buf, int kt) {
        const __half* Ak = Ag + kt * BK;
        const __half* Bk = Bg + kt * BK;
        const uint32_t sa = saA0 + buf * (BM * BK * 2);
        const uint32_t sb = saB0 + buf * (BN * BK * 2);
#pragma unroll
        for (int i = 0; i < 2; ++i) {
            const int r = ldrow + i * 64;
            cp_async16(sa + swz(r, ldch), Ak + (size_t)r * I_ + ldch * 8);
            cp_async16(sb + swz(r, ldch), Bk + (size_t)r * I_ + ldch * 8);
        }
    };

    load_stage(0, 0);
    cp_commit();

    const int KT = I_ / BK;   // 128
    int buf = 0;
    for (int kt = 0; kt < KT; ++kt) {
        if (kt + 1 < KT) {
            load_stage(buf ^ 1, kt + 1);
            cp_commit();
            cp_wait<1>();
        } else {
            cp_wait<0>();
        }
        __syncthreads();

        const uint32_t baseA = saA0 + buf * (BM * BK * 2);
        const uint32_t baseB = saB0 + buf * (BN * BK * 2);

#pragma unroll
        for (int ks = 0; ks < 2; ++ks) {
            uint32_t afr[4][4];
#pragma unroll
            for (int mi = 0; mi < 4; ++mi) {
                const uint32_t row = wm * 64 + mi * 16 + (lane & 7) + (lane & 8);
                const uint32_t ch = ks * 2 + ((lane >> 4) & 1);
                ldmatrix_x4(afr[mi], baseA + swz(row, ch));
            }
            uint32_t bfr[2][4];
#pragma unroll
            for (int np = 0; np < 2; ++np) {
                const uint32_t row =
                    wn * 32 + np * 16 + (lane & 7) + (((lane >> 4) & 1) << 3);
                const uint32_t ch = ks * 2 + ((lane >> 3) & 1);
                ldmatrix_x4(bfr[np], baseB + swz(row, ch));
            }
#pragma unroll
            for (int mi = 0; mi < 4; ++mi) {
#pragma unroll
                for (int ni = 0; ni < 4; ++ni) {
                    mma16816(acc[mi][ni], afr[mi],
                             bfr[ni >> 1][(ni & 1) * 2],
                             bfr[ni >> 1][(ni & 1) * 2 + 1]);
                }
            }
        }
        __syncthreads();
        buf ^= 1;
    }

    // Epilogue: y = sx[row] * acc, fp32 store
#pragma unroll
    for (int mi = 0; mi < 4; ++mi) {
        const int grow = bm * BM + wm * 64 + mi * 16 + (lane >> 2);
        const float s0 = g_sx[grow];
        const float s1 = g_sx[grow + 8];
#pragma unroll
        for (int ni = 0; ni < 4; ++ni) {
            const int gcol = bn * BN + wn * 32 + ni * 8 + (lane & 3) * 2;
            float2 v0, v1;
            v0.x = acc[mi][ni][0] * s0; v0.y = acc[mi][ni][1] * s0;
            v1.x = acc[mi][ni][2] * s1; v1.y = acc[mi][ni][3] * s1;
            *reinterpret_cast<float2*>(C + (size_t)grow * O_ + gcol) = v0;
            *reinterpret_cast<float2*>(C + (size_t)(grow + 8) * O_ + gcol) = v1;
        }
    }
}

// ---------------------------------------------------------------------------
// Launch
// ---------------------------------------------------------------------------
extern "C" void kernel_launch(void* const* d_in, const int* in_sizes, int n_in,
                              void* d_out, int out_size) {
    const float* x = (const float*)d_in[0];
    const int* w = (const int*)d_in[1];
    const float* scales = (const float*)d_in[2];
    const float* zeros = (const float*)d_in[3];
    float* out = (float*)d_out;

    quant_x_kernel<<<T_, 256>>>(x);
    dequant_w_kernel<<<(O_ * (I_ / 8)) / 256, 256>>>(w, scales, zeros);
    gemm_kernel<<<dim3(O_ / BN, T_ / BM), 256>>>(out);
}